// round 15
// baseline (speedup 1.0000x reference)
#include <cuda_runtime.h>

// Aggregation: out[n, g*64+cw, y, x] = sum_{i,j} in[n, g*64+cw, y+i-1, x+j-1]
//                                      * w[n, cw, 3*i+j, y*64+x]
// Shapes: in (16,512,64,64) f32, w (16,64,9,4096) f32, out (16,512,64,64) f32.
// groups = 8, pad = 1, stride = 1, dilation = 1.

#define N_   16
#define CX_  512
#define CW_  64
#define G_   8
#define H_   64
#define W_   64
#define HW_  (H_ * W_)   // 4096
#define KK_  9

__global__ __launch_bounds__(128, 8)
void aggregation_kernel(const float* __restrict__ in,
                        const float* __restrict__ wgt,
                        float* __restrict__ out)
{
    // block: (16, 8) -> tx = float4 column index (x0 = 4*tx), ty = row in tile
    // grid:  (8, 64, 16) -> (y-tile, cw, n)
    const int tx = threadIdx.x;            // 0..15
    const int ty = threadIdx.y;            // 0..7
    const int ytile = blockIdx.x;          // 0..7
    const int cw = blockIdx.y;             // 0..63
    const int n  = blockIdx.z;             // 0..15

    const int y  = ytile * 8 + ty;         // 0..63
    const int x0 = tx * 4;                 // 0,4,...,60
    const int pix = y * W_ + x0;

    // ---- load 9 per-pixel weights (float4 over x), reused across all 8 groups
    const float* wbase = wgt + ((size_t)(n * CW_ + cw) * KK_) * HW_ + pix;
    float4 w[KK_];
#pragma unroll
    for (int kk = 0; kk < KK_; kk++)
        w[kk] = *reinterpret_cast<const float4*>(wbase + kk * HW_);

    const float4 zero4 = make_float4(0.f, 0.f, 0.f, 0.f);
    const bool has_l = (x0 > 0);
    const bool has_r = (x0 + 4 < W_);

#pragma unroll 2
    for (int g = 0; g < G_; g++) {
        const int c = g * CW_ + cw;
        const float* inp  = in  + ((size_t)(n * CX_ + c)) * HW_;
        float*       outp = out + ((size_t)(n * CX_ + c)) * HW_;

        float4 acc = zero4;
#pragma unroll
        for (int i = 0; i < 3; i++) {
            const int r = y + i - 1;
            float4 v;
            float vl, vr;
            if (r >= 0 && r < H_) {
                const float* rp = inp + r * W_ + x0;
                v  = *reinterpret_cast<const float4*>(rp);
                vl = has_l ? rp[-1] : 0.f;
                vr = has_r ? rp[4]  : 0.f;
            } else {
                v = zero4; vl = 0.f; vr = 0.f;
            }
            const float4 w0 = w[i * 3 + 0];
            const float4 w1 = w[i * 3 + 1];
            const float4 w2 = w[i * 3 + 2];
            acc.x += w0.x * vl  + w1.x * v.x + w2.x * v.y;
            acc.y += w0.y * v.x + w1.y * v.y + w2.y * v.z;
            acc.z += w0.z * v.y + w1.z * v.z + w2.z * v.w;
            acc.w += w0.w * v.z + w1.w * v.w + w2.w * vr;
        }
        *reinterpret_cast<float4*>(outp + pix) = acc;
    }
}

extern "C" void kernel_launch(void* const* d_in, const int* in_sizes, int n_in,
                              void* d_out, int out_size)
{
    const float* inp = (const float*)d_in[0];   // (16,512,64,64) f32
    const float* wgt = (const float*)d_in[1];   // (16,64,9,4096) f32
    float* out = (float*)d_out;                 // (16,512,64,64) f32

    dim3 block(16, 8);
    dim3 grid(H_ / 8, CW_, N_);                 // (8, 64, 16)
    aggregation_kernel<<<grid, block>>>(inp, wgt, out);
}

// round 16
// speedup vs baseline: 1.0025x; 1.0025x over previous
#include <cuda_runtime.h>

// Aggregation: out[n, g*64+cw, y, x] = sum_{i,j} in[n, g*64+cw, y+i-1, x+j-1]
//                                      * w[n, cw, 3*i+j, y*64+x]
// Shapes: in (16,512,64,64) f32, w (16,64,9,4096) f32, out (16,512,64,64) f32.
// groups = 8, pad = 1, stride = 1, dilation = 1.

#define N_   16
#define CX_  512
#define CW_  64
#define G_   8
#define H_   64
#define W_   64
#define HW_  (H_ * W_)   // 4096
#define KK_  9

__global__ __launch_bounds__(128, 8)
void aggregation_kernel(const float* __restrict__ in,
                        const float* __restrict__ wgt,
                        float* __restrict__ out)
{
    // block: (16, 8) -> tx = float4 column index (x0 = 4*tx), ty = row in tile
    // grid:  (8, 64, 16) -> (y-tile, cw, n)
    const int tx = threadIdx.x;            // 0..15
    const int ty = threadIdx.y;            // 0..7
    const int ytile = blockIdx.x;          // 0..7
    const int cw = blockIdx.y;             // 0..63
    const int n  = blockIdx.z;             // 0..15

    const int y  = ytile * 8 + ty;         // 0..63
    const int x0 = tx * 4;                 // 0,4,...,60
    const int pix = y * W_ + x0;

    // ---- load 9 per-pixel weights (float4 over x), reused across all 8 groups
    const float* wbase = wgt + ((size_t)(n * CW_ + cw) * KK_) * HW_ + pix;
    float4 w[KK_];
#pragma unroll
    for (int kk = 0; kk < KK_; kk++)
        w[kk] = *reinterpret_cast<const float4*>(wbase + kk * HW_);

    const float4 zero4 = make_float4(0.f, 0.f, 0.f, 0.f);
    const bool has_l = (x0 > 0);
    const bool has_r = (x0 + 4 < W_);

#pragma unroll 2
    for (int g = 0; g < G_; g++) {
        const int c = g * CW_ + cw;
        const float* inp  = in  + ((size_t)(n * CX_ + c)) * HW_;
        float*       outp = out + ((size_t)(n * CX_ + c)) * HW_;

        float4 acc = zero4;
#pragma unroll
        for (int i = 0; i < 3; i++) {
            const int r = y + i - 1;
            float4 v;
            float vl, vr;
            if (r >= 0 && r < H_) {
                const float* rp = inp + r * W_ + x0;
                v  = *reinterpret_cast<const float4*>(rp);
                vl = has_l ? rp[-1] : 0.f;
                vr = has_r ? rp[4]  : 0.f;
            } else {
                v = zero4; vl = 0.f; vr = 0.f;
            }
            const float4 w0 = w[i * 3 + 0];
            const float4 w1 = w[i * 3 + 1];
            const float4 w2 = w[i * 3 + 2];
            acc.x += w0.x * vl  + w1.x * v.x + w2.x * v.y;
            acc.y += w0.y * v.x + w1.y * v.y + w2.y * v.z;
            acc.z += w0.z * v.y + w1.z * v.z + w2.z * v.w;
            acc.w += w0.w * v.z + w1.w * v.w + w2.w * vr;
        }
        *reinterpret_cast<float4*>(outp + pix) = acc;
    }
}

extern "C" void kernel_launch(void* const* d_in, const int* in_sizes, int n_in,
                              void* d_out, int out_size)
{
    const float* inp = (const float*)d_in[0];   // (16,512,64,64) f32
    const float* wgt = (const float*)d_in[1];   // (16,64,9,4096) f32
    float* out = (float*)d_out;                 // (16,512,64,64) f32

    dim3 block(16, 8);
    dim3 grid(H_ / 8, CW_, N_);                 // (8, 64, 16)
    aggregation_kernel<<<grid, block>>>(inp, wgt, out);
}